// round 15
// baseline (speedup 1.0000x reference)
#include <cuda_runtime.h>
#include <cstdint>

#define EMB 64
#define MAXN 200000
#define MAXB 16384

// Scratch (static __device__ globals: allocation-free). R8-proven layout.
__device__ float  g_hacc[2][(size_t)MAXN * EMB];    // sum of exp(e)*src_feat per dst node
__device__ float2 g_ds[2][MAXN];                    // .x = s_dst score, .y = sum of exp(e)
__device__ unsigned char g_flag[2][MAXN];           // 1 if node is in the batch
__device__ float  g_z[2][(size_t)MAXB * EMB];       // z_self = relu(Ws@emb+bs) per batch row

// ---------------------------------------------------------------------------
// K1: per (side, batch element): mark flag, zero accumulators, compute s_dst.
// One warp per (side, b). Duplicate ids write identical values (benign).
// ---------------------------------------------------------------------------
__global__ void __launch_bounds__(256)
prep_kernel(const float* __restrict__ utab, const float* __restrict__ itab,
            const float* __restrict__ Wa_u, const float* __restrict__ Wa_i,
            const int* __restrict__ uids, const int* __restrict__ iids, int B)
{
    int gw = (blockIdx.x * blockDim.x + threadIdx.x) >> 5;
    int lane = threadIdx.x & 31;
    if (gw >= 2 * B) return;
    int side = gw >= B ? 1 : 0;
    int b = side ? gw - B : gw;
    int id = side ? iids[b] : uids[b];
    const float* tab = side ? itab : utab;
    const float* wa = (side ? Wa_i : Wa_u) + EMB;   // dst half of attention vector

    float2 v = *(const float2*)(tab + (size_t)id * EMB + 2 * lane);
    float p = v.x * wa[2 * lane] + v.y * wa[2 * lane + 1];
    #pragma unroll
    for (int o = 16; o; o >>= 1) p += __shfl_xor_sync(0xffffffffu, p, o);

    *(float2*)(&g_hacc[side][(size_t)id * EMB + 2 * lane]) = make_float2(0.f, 0.f);
    if (lane == 0) {
        g_ds[side][id] = make_float2(p, 0.f);
        g_flag[side][id] = 1;
    }
}

// ---------------------------------------------------------------------------
// K2 COMBO: grid.x = GB self-GEMM blocks, then EB edge blocks; grid.y = side.
// Self-GEMM blocks (FFMA-dense) overlap with edge blocks (memory/atomic
// bound) across SMs inside one launch -> the z_self GEMM runs "for free"
// in the edge kernel's shadow. Edge part = exact R8 winner (46us measured).
// ---------------------------------------------------------------------------
__global__ void __launch_bounds__(256)
combo_kernel(const float* __restrict__ utab, const float* __restrict__ itab,
             const float* __restrict__ Wa_u, const float* __restrict__ Wa_i,
             const float* __restrict__ Ws_u, const float* __restrict__ bs_u,
             const float* __restrict__ Ws_i, const float* __restrict__ bs_i,
             const int* __restrict__ uids, const int* __restrict__ iids,
             const int* __restrict__ src_iu, const int* __restrict__ dst_iu,
             const int* __restrict__ src_ui, const int* __restrict__ dst_ui,
             int B, int E, int GB)
{
    __shared__ float WT[64 * 68];    // GEMM branch only; edge blocks ignore
    __shared__ float vec[64 * 68];
    __shared__ int   ids_s[64];

    int side = blockIdx.y;
    int tid = threadIdx.x;

    if (blockIdx.x < GB) {
        // ----- self-GEMM branch: z_s = relu(Ws @ emb + bs), 64 rows -----
        const float* tab = side ? itab : utab;
        const float* Ws = side ? Ws_i : Ws_u;
        const float* bsv = side ? bs_i : bs_u;
        const int* ids = side ? iids : uids;

        if (tid < 64) {
            int b = blockIdx.x * 64 + tid; if (b >= B) b = B - 1;
            ids_s[tid] = ids[b];
        }
        for (int t = tid; t < 1024; t += 256) {          // Ws^T into smem
            int o = t >> 4, kg = t & 15;
            float4 w = *(const float4*)&Ws[o * 64 + 4 * kg];
            WT[(4 * kg + 0) * 68 + o] = w.x;
            WT[(4 * kg + 1) * 68 + o] = w.y;
            WT[(4 * kg + 2) * 68 + o] = w.z;
            WT[(4 * kg + 3) * 68 + o] = w.w;
        }
        __syncthreads();
        for (int t = tid; t < 1024; t += 256) {          // gather emb rows
            int row = t >> 4, k0 = (t & 15) * 4;
            *(float4*)&vec[row * 68 + k0] =
                *(const float4*)&tab[(size_t)ids_s[row] * EMB + k0];
        }
        __syncthreads();

        int tx = tid & 15, ty = tid >> 4;                // 4 rows x 4 cols
        float acc[4][4] = {};
        #pragma unroll 8
        for (int k = 0; k < 64; k++) {
            float4 w = *(const float4*)&WT[k * 68 + 4 * tx];
            #pragma unroll
            for (int r = 0; r < 4; r++) {
                float a = vec[(4 * ty + r) * 68 + k];
                acc[r][0] += a * w.x; acc[r][1] += a * w.y;
                acc[r][2] += a * w.z; acc[r][3] += a * w.w;
            }
        }
        float4 b4 = *(const float4*)&bsv[4 * tx];
        #pragma unroll
        for (int r = 0; r < 4; r++) {
            int b = blockIdx.x * 64 + 4 * ty + r;
            if (b >= B) continue;
            float4 o;
            o.x = fmaxf(acc[r][0] + b4.x, 0.f);
            o.y = fmaxf(acc[r][1] + b4.y, 0.f);
            o.z = fmaxf(acc[r][2] + b4.z, 0.f);
            o.w = fmaxf(acc[r][3] + b4.w, 0.f);
            *(float4*)&g_z[side][(size_t)b * EMB + 4 * tx] = o;
        }
    } else {
        // ----- edge branch: exact R8 filtered scatter -----
        const float* stab = side ? utab : itab;
        const float* wa = side ? Wa_i : Wa_u;
        const int* src = side ? src_ui : src_iu;
        const int* dst = side ? dst_ui : dst_iu;
        const unsigned char* flag = g_flag[side];

        int lane = tid & 31;
        float wx = wa[2 * lane], wy = wa[2 * lane + 1];
        int warp = ((blockIdx.x - GB) * 256 + tid) >> 5;
        int idx = warp * 32 + lane;

        int d = 0, s = 0, f = 0;
        if (idx < E) {
            d = dst[idx];
            f = flag[d];
            s = src[idx];
        }
        unsigned m = __ballot_sync(0xffffffffu, f);

        while (m) {
            int j = __ffs(m) - 1; m &= m - 1;
            int ds = __shfl_sync(0xffffffffu, d, j);
            int ss = __shfl_sync(0xffffffffu, s, j);

            float2 v = *(const float2*)(stab + (size_t)ss * EMB + 2 * lane);
            float p = v.x * wx + v.y * wy;
            #pragma unroll
            for (int o = 16; o; o >>= 1) p += __shfl_xor_sync(0xffffffffu, p, o);

            float e = p + g_ds[side][ds].x;
            e = e >= 0.f ? e : 0.01f * e;      // leaky_relu(., 0.01)
            float ex = __expf(e);

            if (lane == 0) atomicAdd(&g_ds[side][ds].y, ex);
            float* hp = &g_hacc[side][(size_t)ds * EMB + 2 * lane];
            asm volatile("red.global.add.v2.f32 [%0], {%1, %2};"
                         :: "l"(hp), "f"(v.x * ex), "f"(v.y * ex) : "memory");
        }
    }
}

// ---------------------------------------------------------------------------
// K3: dependent MLP rest. 64 rows/block, 256 threads, dynamic smem 51.2KB:
//   zbuf[64][132]: cols 0-63 = z_s (from g_z), 64-127 = h -> then z_n.
//   wbuf[64][68]:  Wn, then Wfc chunks.
// ---------------------------------------------------------------------------
__global__ void __launch_bounds__(256)
mlp_rest_kernel(const float* __restrict__ Wn_u, const float* __restrict__ bn_u,
                const float* __restrict__ Wn_i, const float* __restrict__ bn_i,
                const float* __restrict__ Wfc_u, const float* __restrict__ Wfc_i,
                const int* __restrict__ uids, const int* __restrict__ iids,
                float* __restrict__ out, int B)
{
    extern __shared__ float sm[];
    float* zbuf = sm;              // 64 * 132
    float* wbuf = sm + 64 * 132;   // 64 * 68
    __shared__ int   ids_s[64];
    __shared__ float rden_s[64];

    int side = blockIdx.y;
    const float* Wn = side ? Wn_i : Wn_u;
    const float* bnv = side ? bn_i : bn_u;
    const float* Wfc = side ? Wfc_i : Wfc_u;
    const int* ids = side ? iids : uids;

    int tid = threadIdx.x;
    int tx = tid & 15, ty = tid >> 4;   // 4 cols x 4 rows per thread

    if (tid < 64) {
        int b = blockIdx.x * 64 + tid; if (b >= B) b = B - 1;
        int id = ids[b];
        ids_s[tid] = id;
        float den = g_ds[side][id].y;
        rden_s[tid] = den > 0.f ? 1.f / den : 0.f;
    }
    for (int t = tid; t < 1024; t += 256) {      // Wn^T into smem
        int o = t >> 4, kg = t & 15;
        float4 w = *(const float4*)&Wn[o * 64 + 4 * kg];
        wbuf[(4 * kg + 0) * 68 + o] = w.x;
        wbuf[(4 * kg + 1) * 68 + o] = w.y;
        wbuf[(4 * kg + 2) * 68 + o] = w.z;
        wbuf[(4 * kg + 3) * 68 + o] = w.w;
    }
    __syncthreads();
    // Load z_s (coalesced) and h (gather + normalize): 64 rows x 32 groups.
    for (int t = tid; t < 2048; t += 256) {
        int row = t >> 5, g = t & 31, k0 = g * 4;
        int brow = blockIdx.x * 64 + row; if (brow >= B) brow = B - 1;
        float4 v;
        if (g < 16) {
            v = *(const float4*)&g_z[side][(size_t)brow * EMB + k0];
        } else {
            int id = ids_s[row];
            v = *(const float4*)&g_hacc[side][(size_t)id * EMB + (k0 - 64)];
            float r = rden_s[row];
            v.x *= r; v.y *= r; v.z *= r; v.w *= r;
        }
        *(float4*)&zbuf[row * 132 + k0] = v;
    }
    __syncthreads();

    // z_n = relu(Wn @ h + bn)
    float accN[4][4] = {};
    #pragma unroll 8
    for (int k = 0; k < 64; k++) {
        float4 w = *(const float4*)&wbuf[k * 68 + 4 * tx];
        #pragma unroll
        for (int r = 0; r < 4; r++) {
            float a = zbuf[(4 * ty + r) * 132 + 64 + k];
            accN[r][0] += a * w.x; accN[r][1] += a * w.y;
            accN[r][2] += a * w.z; accN[r][3] += a * w.w;
        }
    }
    __syncthreads();   // all h reads done before overwrite with z_n
    float4 bN = *(const float4*)&bnv[4 * tx];
    #pragma unroll
    for (int r = 0; r < 4; r++) {
        float4 zn;
        zn.x = fmaxf(accN[r][0] + bN.x, 0.f);
        zn.y = fmaxf(accN[r][1] + bN.y, 0.f);
        zn.z = fmaxf(accN[r][2] + bN.z, 0.f);
        zn.w = fmaxf(accN[r][3] + bN.w, 0.f);
        *(float4*)&zbuf[(4 * ty + r) * 132 + 64 + 4 * tx] = zn;
    }
    __syncthreads();

    // out = relu(Wfc @ [z_s ; z_n]), k=128 in two chunks.
    float acc2[4][4] = {};
    #pragma unroll
    for (int kc = 0; kc < 2; kc++) {
        for (int t = tid; t < 1024; t += 256) {
            int o = t >> 4, kg = t & 15;
            float4 w = *(const float4*)&Wfc[o * 128 + kc * 64 + 4 * kg];
            wbuf[(4 * kg + 0) * 68 + o] = w.x;
            wbuf[(4 * kg + 1) * 68 + o] = w.y;
            wbuf[(4 * kg + 2) * 68 + o] = w.z;
            wbuf[(4 * kg + 3) * 68 + o] = w.w;
        }
        __syncthreads();
        #pragma unroll 8
        for (int k = 0; k < 64; k++) {
            float4 w = *(const float4*)&wbuf[k * 68 + 4 * tx];
            #pragma unroll
            for (int r = 0; r < 4; r++) {
                float a = zbuf[(4 * ty + r) * 132 + kc * 64 + k];
                acc2[r][0] += a * w.x; acc2[r][1] += a * w.y;
                acc2[r][2] += a * w.z; acc2[r][3] += a * w.w;
            }
        }
        __syncthreads();
    }

    #pragma unroll
    for (int r = 0; r < 4; r++) {
        int b = blockIdx.x * 64 + 4 * ty + r;
        if (b >= B) continue;
        float4 o;
        o.x = fmaxf(acc2[r][0], 0.f);
        o.y = fmaxf(acc2[r][1], 0.f);
        o.z = fmaxf(acc2[r][2], 0.f);
        o.w = fmaxf(acc2[r][3], 0.f);
        *(float4*)&out[(size_t)b * 2 * EMB + side * EMB + 4 * tx] = o;
    }
}

// ---------------------------------------------------------------------------
extern "C" void kernel_launch(void* const* d_in, const int* in_sizes, int n_in,
                              void* d_out, int out_size)
{
    const float* user_emb = (const float*)d_in[0];
    const float* item_emb = (const float*)d_in[1];
    const float* Wa_u = (const float*)d_in[2];
    const float* Wa_i = (const float*)d_in[3];
    const float* Wfc_u = (const float*)d_in[4];
    const float* Wfc_i = (const float*)d_in[5];
    const float* Ws_u = (const float*)d_in[6];
    const float* bs_u = (const float*)d_in[7];
    const float* Ws_i = (const float*)d_in[8];
    const float* bs_i = (const float*)d_in[9];
    const float* Wn_u = (const float*)d_in[10];
    const float* bn_u = (const float*)d_in[11];
    const float* Wn_i = (const float*)d_in[12];
    const float* bn_i = (const float*)d_in[13];
    const int* u      = (const int*)d_in[14];
    const int* ii     = (const int*)d_in[15];
    const int* src_iu = (const int*)d_in[16];
    const int* dst_iu = (const int*)d_in[17];
    const int* src_ui = (const int*)d_in[18];
    const int* dst_ui = (const int*)d_in[19];
    int B = in_sizes[14];
    int E = in_sizes[16];
    float* out = (float*)d_out;

    {   // K1: flag + zero + dst scores.
        int blocks = (2 * B * 32 + 255) / 256;
        prep_kernel<<<blocks, 256>>>(user_emb, item_emb, Wa_u, Wa_i, u, ii, B);
    }
    {   // K2: self-GEMM blocks + edge blocks in ONE launch (overlap).
        int GB = (B + 63) / 64;
        int EB = (E + 255) / 256;
        dim3 g(GB + EB, 2);
        combo_kernel<<<g, 256>>>(user_emb, item_emb, Wa_u, Wa_i,
                                 Ws_u, bs_u, Ws_i, bs_i, u, ii,
                                 src_iu, dst_iu, src_ui, dst_ui, B, E, GB);
    }
    {   // K3: dependent MLP rest (Wn + Wfc), dynamic smem.
        const int SMEM_K3 = (64 * 132 + 64 * 68) * 4;   // 51200 B
        cudaFuncSetAttribute(mlp_rest_kernel,
                             cudaFuncAttributeMaxDynamicSharedMemorySize, SMEM_K3);
        dim3 g((B + 63) / 64, 2);
        mlp_rest_kernel<<<g, 256, SMEM_K3>>>(Wn_u, bn_u, Wn_i, bn_i,
                                             Wfc_u, Wfc_i, u, ii, out, B);
    }
}

// round 16
// speedup vs baseline: 1.2249x; 1.2249x over previous
#include <cuda_runtime.h>
#include <cstdint>

#define EMB 64
#define MAXN 200000
#define MAXB 16384

// Scratch (static __device__ globals: allocation-free). R8-proven layout.
__device__ float  g_hacc[2][(size_t)MAXN * EMB];    // sum of exp(e)*src_feat per dst node
__device__ float2 g_ds[2][MAXN];                    // .x = s_dst score, .y = sum of exp(e)
__device__ unsigned char g_flag[2][MAXN];           // 1 if node is in the batch
__device__ float  g_z[2][(size_t)MAXB * EMB];       // z_self = relu(Ws@emb+bs) per batch row

// ---------------------------------------------------------------------------
// K1: per (side, batch element): mark flag, zero accumulators, compute s_dst.
// One warp per (side, b). (Exact R8 configuration.)
// ---------------------------------------------------------------------------
__global__ void __launch_bounds__(256)
prep_kernel(const float* __restrict__ utab, const float* __restrict__ itab,
            const float* __restrict__ Wa_u, const float* __restrict__ Wa_i,
            const int* __restrict__ uids, const int* __restrict__ iids, int B)
{
    int gw = (blockIdx.x * blockDim.x + threadIdx.x) >> 5;
    int lane = threadIdx.x & 31;
    if (gw >= 2 * B) return;
    int side = gw >= B ? 1 : 0;
    int b = side ? gw - B : gw;
    int id = side ? iids[b] : uids[b];
    const float* tab = side ? itab : utab;
    const float* wa = (side ? Wa_i : Wa_u) + EMB;   // dst half of attention vector

    float2 v = *(const float2*)(tab + (size_t)id * EMB + 2 * lane);
    float p = v.x * wa[2 * lane] + v.y * wa[2 * lane + 1];
    #pragma unroll
    for (int o = 16; o; o >>= 1) p += __shfl_xor_sync(0xffffffffu, p, o);

    *(float2*)(&g_hacc[side][(size_t)id * EMB + 2 * lane]) = make_float2(0.f, 0.f);
    if (lane == 0) {
        g_ds[side][id] = make_float2(p, 0.f);
        g_flag[side][id] = 1;
    }
}

// ---------------------------------------------------------------------------
// K2: edge pass (exact R8 winner, 46us measured). Whole-warp float2 gather,
// 5-shfl dot, red.global.add.v2.f32 scatter.
// ---------------------------------------------------------------------------
__global__ void __launch_bounds__(256)
edge_kernel(const float* __restrict__ utab, const float* __restrict__ itab,
            const float* __restrict__ Wa_u, const float* __restrict__ Wa_i,
            const int* __restrict__ src_iu, const int* __restrict__ dst_iu,
            const int* __restrict__ src_ui, const int* __restrict__ dst_ui,
            int E)
{
    int side = blockIdx.y;
    const float* stab = side ? utab : itab;
    const float* wa = side ? Wa_i : Wa_u;
    const int* src = side ? src_ui : src_iu;
    const int* dst = side ? dst_ui : dst_iu;
    const unsigned char* flag = g_flag[side];

    int lane = threadIdx.x & 31;
    float wx = wa[2 * lane], wy = wa[2 * lane + 1];

    int warp = (blockIdx.x * blockDim.x + threadIdx.x) >> 5;
    int idx = warp * 32 + lane;

    int d = 0, s = 0, f = 0;
    if (idx < E) {
        d = dst[idx];
        f = flag[d];
        s = src[idx];
    }
    unsigned m = __ballot_sync(0xffffffffu, f);

    while (m) {
        int j = __ffs(m) - 1; m &= m - 1;
        int ds = __shfl_sync(0xffffffffu, d, j);
        int ss = __shfl_sync(0xffffffffu, s, j);

        float2 v = *(const float2*)(stab + (size_t)ss * EMB + 2 * lane);
        float p = v.x * wx + v.y * wy;
        #pragma unroll
        for (int o = 16; o; o >>= 1) p += __shfl_xor_sync(0xffffffffu, p, o);

        float e = p + g_ds[side][ds].x;
        e = e >= 0.f ? e : 0.01f * e;          // leaky_relu(., 0.01)
        float ex = __expf(e);

        if (lane == 0) atomicAdd(&g_ds[side][ds].y, ex);
        float* hp = &g_hacc[side][(size_t)ds * EMB + 2 * lane];
        asm volatile("red.global.add.v2.f32 [%0], {%1, %2};"
                     :: "l"(hp), "f"(v.x * ex), "f"(v.y * ex) : "memory");
    }
}

// ---------------------------------------------------------------------------
// K-zs (side stream): z_s = relu(Ws @ emb + bs). Independent of prep/edge;
// runs concurrently with them on the forked stream. 64 rows, 256 threads.
// ---------------------------------------------------------------------------
__global__ void __launch_bounds__(256)
zs_kernel(const float* __restrict__ utab, const float* __restrict__ itab,
          const float* __restrict__ Ws_u, const float* __restrict__ bs_u,
          const float* __restrict__ Ws_i, const float* __restrict__ bs_i,
          const int* __restrict__ uids, const int* __restrict__ iids, int B)
{
    __shared__ float WT[64 * 68];
    __shared__ float vec[64 * 68];
    __shared__ int   ids_s[64];

    int side = blockIdx.y;
    const float* tab = side ? itab : utab;
    const float* Ws = side ? Ws_i : Ws_u;
    const float* bsv = side ? bs_i : bs_u;
    const int* ids = side ? iids : uids;

    int tid = threadIdx.x;
    if (tid < 64) {
        int b = blockIdx.x * 64 + tid; if (b >= B) b = B - 1;
        ids_s[tid] = ids[b];
    }
    for (int t = tid; t < 1024; t += 256) {
        int o = t >> 4, kg = t & 15;
        float4 w = *(const float4*)&Ws[o * 64 + 4 * kg];
        WT[(4 * kg + 0) * 68 + o] = w.x;
        WT[(4 * kg + 1) * 68 + o] = w.y;
        WT[(4 * kg + 2) * 68 + o] = w.z;
        WT[(4 * kg + 3) * 68 + o] = w.w;
    }
    __syncthreads();
    for (int t = tid; t < 1024; t += 256) {
        int row = t >> 4, k0 = (t & 15) * 4;
        *(float4*)&vec[row * 68 + k0] =
            *(const float4*)&tab[(size_t)ids_s[row] * EMB + k0];
    }
    __syncthreads();

    int tx = tid & 15, ty = tid >> 4;
    float acc[4][4] = {};
    #pragma unroll 8
    for (int k = 0; k < 64; k++) {
        float4 w = *(const float4*)&WT[k * 68 + 4 * tx];
        #pragma unroll
        for (int r = 0; r < 4; r++) {
            float a = vec[(4 * ty + r) * 68 + k];
            acc[r][0] += a * w.x; acc[r][1] += a * w.y;
            acc[r][2] += a * w.z; acc[r][3] += a * w.w;
        }
    }
    float4 b4 = *(const float4*)&bsv[4 * tx];
    #pragma unroll
    for (int r = 0; r < 4; r++) {
        int b = blockIdx.x * 64 + 4 * ty + r;
        if (b >= B) continue;
        float4 o;
        o.x = fmaxf(acc[r][0] + b4.x, 0.f);
        o.y = fmaxf(acc[r][1] + b4.y, 0.f);
        o.z = fmaxf(acc[r][2] + b4.z, 0.f);
        o.w = fmaxf(acc[r][3] + b4.w, 0.f);
        *(float4*)&g_z[side][(size_t)b * EMB + 4 * tx] = o;
    }
}

// ---------------------------------------------------------------------------
// K3: dependent MLP rest = R14 fused MLP minus the Ws stage. 32 rows,
// 128 threads, 4x4 register tiles (proven shape). z_s read from g_z.
// ---------------------------------------------------------------------------
__global__ void __launch_bounds__(128)
mlp_rest_kernel(const float* __restrict__ Wn_u, const float* __restrict__ bn_u,
                const float* __restrict__ Wn_i, const float* __restrict__ bn_i,
                const float* __restrict__ Wfc_u, const float* __restrict__ Wfc_i,
                const int* __restrict__ uids, const int* __restrict__ iids,
                float* __restrict__ out, int B)
{
    int side = blockIdx.y;
    const float* Wn = side ? Wn_i : Wn_u;
    const float* bnv = side ? bn_i : bn_u;
    const float* Wfc = side ? Wfc_i : Wfc_u;
    const int* ids = side ? iids : uids;

    __shared__ float ibuf[32 * 132];   // cols 0-63: z_s, 64-127: h -> z_n
    __shared__ float wbuf[64 * 68];
    __shared__ int   ids_s[32];
    __shared__ float rden_s[32];

    int tid = threadIdx.x;
    int tx = tid & 15, ty = tid >> 4;

    if (tid < 32) {
        int b = blockIdx.x * 32 + tid; if (b >= B) b = B - 1;
        int id = ids[b];
        ids_s[tid] = id;
        float den = g_ds[side][id].y;
        rden_s[tid] = den > 0.f ? 1.f / den : 0.f;
    }
    for (int t = tid; t < 1024; t += 128) {      // Wn^T into smem
        int o = t >> 4, kg = t & 15;
        float4 w = *(const float4*)&Wn[o * 64 + 4 * kg];
        wbuf[(4 * kg + 0) * 68 + o] = w.x;
        wbuf[(4 * kg + 1) * 68 + o] = w.y;
        wbuf[(4 * kg + 2) * 68 + o] = w.z;
        wbuf[(4 * kg + 3) * 68 + o] = w.w;
    }
    __syncthreads();
    // Load z_s (coalesced from g_z) and h (gather + normalize).
    for (int t = tid; t < 1024; t += 128) {
        int row = t >> 5, g = t & 31, k0 = g * 4;
        float4 v;
        if (g < 16) {
            int brow = blockIdx.x * 32 + row; if (brow >= B) brow = B - 1;
            v = *(const float4*)&g_z[side][(size_t)brow * EMB + k0];
        } else {
            v = *(const float4*)&g_hacc[side][(size_t)ids_s[row] * EMB + (k0 - 64)];
            float r = rden_s[row];
            v.x *= r; v.y *= r; v.z *= r; v.w *= r;
        }
        *(float4*)&ibuf[row * 132 + k0] = v;
    }
    __syncthreads();

    // z_n = relu(Wn @ h + bn)
    float accN[4][4] = {};
    #pragma unroll 8
    for (int k = 0; k < 64; k++) {
        float4 w = *(const float4*)&wbuf[k * 68 + 4 * tx];
        #pragma unroll
        for (int r = 0; r < 4; r++) {
            float a = ibuf[(4 * ty + r) * 132 + 64 + k];
            accN[r][0] += a * w.x; accN[r][1] += a * w.y;
            accN[r][2] += a * w.z; accN[r][3] += a * w.w;
        }
    }
    __syncthreads();   // all h reads done before overwrite with z_n
    float4 bN = *(const float4*)&bnv[4 * tx];
    #pragma unroll
    for (int r = 0; r < 4; r++) {
        float4 zn;
        zn.x = fmaxf(accN[r][0] + bN.x, 0.f);
        zn.y = fmaxf(accN[r][1] + bN.y, 0.f);
        zn.z = fmaxf(accN[r][2] + bN.z, 0.f);
        zn.w = fmaxf(accN[r][3] + bN.w, 0.f);
        *(float4*)&ibuf[(4 * ty + r) * 132 + 64 + 4 * tx] = zn;
    }
    __syncthreads();

    // out = relu(Wfc @ [z_s ; z_n]), k=128 in two chunks.
    float acc2[4][4] = {};
    #pragma unroll
    for (int kc = 0; kc < 2; kc++) {
        for (int t = tid; t < 1024; t += 128) {
            int o = t >> 4, kg = t & 15;
            float4 w = *(const float4*)&Wfc[o * 128 + kc * 64 + 4 * kg];
            wbuf[(4 * kg + 0) * 68 + o] = w.x;
            wbuf[(4 * kg + 1) * 68 + o] = w.y;
            wbuf[(4 * kg + 2) * 68 + o] = w.z;
            wbuf[(4 * kg + 3) * 68 + o] = w.w;
        }
        __syncthreads();
        #pragma unroll 8
        for (int k = 0; k < 64; k++) {
            float4 w = *(const float4*)&wbuf[k * 68 + 4 * tx];
            #pragma unroll
            for (int r = 0; r < 4; r++) {
                float a = ibuf[(4 * ty + r) * 132 + kc * 64 + k];
                acc2[r][0] += a * w.x; acc2[r][1] += a * w.y;
                acc2[r][2] += a * w.z; acc2[r][3] += a * w.w;
            }
        }
        __syncthreads();
    }

    #pragma unroll
    for (int r = 0; r < 4; r++) {
        int b = blockIdx.x * 32 + 4 * ty + r;
        if (b >= B) continue;
        float4 o;
        o.x = fmaxf(acc2[r][0], 0.f);
        o.y = fmaxf(acc2[r][1], 0.f);
        o.z = fmaxf(acc2[r][2], 0.f);
        o.w = fmaxf(acc2[r][3], 0.f);
        *(float4*)&out[(size_t)b * 2 * EMB + side * EMB + 4 * tx] = o;
    }
}

// ---------------------------------------------------------------------------
extern "C" void kernel_launch(void* const* d_in, const int* in_sizes, int n_in,
                              void* d_out, int out_size)
{
    const float* user_emb = (const float*)d_in[0];
    const float* item_emb = (const float*)d_in[1];
    const float* Wa_u = (const float*)d_in[2];
    const float* Wa_i = (const float*)d_in[3];
    const float* Wfc_u = (const float*)d_in[4];
    const float* Wfc_i = (const float*)d_in[5];
    const float* Ws_u = (const float*)d_in[6];
    const float* bs_u = (const float*)d_in[7];
    const float* Ws_i = (const float*)d_in[8];
    const float* bs_i = (const float*)d_in[9];
    const float* Wn_u = (const float*)d_in[10];
    const float* bn_u = (const float*)d_in[11];
    const float* Wn_i = (const float*)d_in[12];
    const float* bn_i = (const float*)d_in[13];
    const int* u      = (const int*)d_in[14];
    const int* ii     = (const int*)d_in[15];
    const int* src_iu = (const int*)d_in[16];
    const int* dst_iu = (const int*)d_in[17];
    const int* src_ui = (const int*)d_in[18];
    const int* dst_ui = (const int*)d_in[19];
    int B = in_sizes[14];
    int E = in_sizes[16];
    float* out = (float*)d_out;

    // Fork a side stream into the capture for the independent z_s GEMM.
    // Created per call and intentionally not destroyed (destroying a forked
    // stream/event mid-capture can invalidate the capture; no device memory
    // is involved, and kernel_launch runs only twice per process).
    cudaStream_t s1;
    cudaEvent_t eFork, eJoin;
    cudaStreamCreateWithFlags(&s1, cudaStreamNonBlocking);
    cudaEventCreateWithFlags(&eFork, cudaEventDisableTiming);
    cudaEventCreateWithFlags(&eJoin, cudaEventDisableTiming);

    cudaEventRecord(eFork, 0);
    cudaStreamWaitEvent(s1, eFork, 0);
    {   // side stream: z_s = relu(Ws@emb+bs), overlaps prep + edge.
        dim3 g((B + 63) / 64, 2);
        zs_kernel<<<g, 256, 0, s1>>>(user_emb, item_emb, Ws_u, bs_u, Ws_i, bs_i,
                                     u, ii, B);
    }
    cudaEventRecord(eJoin, s1);

    {   // main stream: K1 flag + zero + dst scores.
        int blocks = (2 * B * 32 + 255) / 256;
        prep_kernel<<<blocks, 256>>>(user_emb, item_emb, Wa_u, Wa_i, u, ii, B);
    }
    {   // main stream: K2 filtered edge scatter.
        int blocks = (E + 8 * 32 - 1) / (8 * 32);
        dim3 g(blocks, 2);
        edge_kernel<<<g, 256>>>(user_emb, item_emb, Wa_u, Wa_i,
                                src_iu, dst_iu, src_ui, dst_ui, E);
    }
    cudaStreamWaitEvent(0, eJoin, 0);   // join: mlp_rest needs g_z
    {   // main stream: K3 dependent MLP rest (Wn + Wfc).
        dim3 g((B + 31) / 32, 2);
        mlp_rest_kernel<<<g, 128>>>(Wn_u, bn_u, Wn_i, bn_i, Wfc_u, Wfc_i,
                                    u, ii, out, B);
    }
}